// round 1
// baseline (speedup 1.0000x reference)
#include <cuda_runtime.h>

#define Bb 8
#define Nn 2048
#define Ff 64
#define NEG_BIG (-9000000000000000.0f)
#define ALPHA 0.2f

// Scratch (no allocation allowed -> device globals)
__device__ float g_Wh[Bb * Nn * Ff];   // 4 MB
__device__ float g_s[Bb * Nn];
__device__ float g_t[Bb * Nn];
__device__ float g_m[Bb * Nn];
__device__ float g_linv[Bb * Nn];

// ---------------------------------------------------------------------------
// Kernel A: Wh = h @ W ; s = Wh @ a1 ; t = Wh @ a2
// 256 threads, 4 rows per block, thread (r = t/64, o = t%64)
// ---------------------------------------------------------------------------
__global__ void __launch_bounds__(256) kA(const float* __restrict__ h,
                                          const float* __restrict__ W,
                                          const float* __restrict__ a) {
    __shared__ float Wsh[64 * 64];
    __shared__ float hsh[4][64];
    __shared__ float spart[4][2];
    __shared__ float tpart[4][2];

    int t = threadIdx.x;
    int r = t >> 6;
    int o = t & 63;
    int row = blockIdx.x * 4 + r;   // global row in [0, B*N)

#pragma unroll
    for (int k = 0; k < 16; k++) Wsh[t + 256 * k] = W[t + 256 * k];
    hsh[r][o] = h[row * 64 + o];
    __syncthreads();

    float wh = 0.0f;
#pragma unroll
    for (int f = 0; f < 64; f++) wh += hsh[r][f] * Wsh[f * 64 + o];
    g_Wh[row * 64 + o] = wh;

    float sv = wh * a[o];
    float tv = wh * a[64 + o];
#pragma unroll
    for (int off = 16; off; off >>= 1) {
        sv += __shfl_down_sync(0xffffffffu, sv, off);
        tv += __shfl_down_sync(0xffffffffu, tv, off);
    }
    int lane = t & 31;
    int half = (t >> 5) & 1;
    if (lane == 0) { spart[r][half] = sv; tpart[r][half] = tv; }
    __syncthreads();
    if (o == 0) {
        g_s[row] = spart[r][0] + spart[r][1];
        g_t[row] = tpart[r][0] + tpart[r][1];
    }
}

// ---------------------------------------------------------------------------
// Kernel C: per attention row: m = max_j masked_lrelu(s_i + t_j),
//           linv = 1 / sum_j exp(e - m).  One block (256 thr) per row.
// ---------------------------------------------------------------------------
__global__ void __launch_bounds__(256) kC(const int* __restrict__ adj) {
    __shared__ float esh[Nn];
    __shared__ float red[256];

    int t = threadIdx.x;
    int row = blockIdx.x;                    // b*N + i
    int tb = (row / Nn) * Nn;                // base of g_t for this batch
    const int* __restrict__ arow = adj + (long long)row * Nn;

    float s = g_s[row];
    float mx = NEG_BIG;
#pragma unroll
    for (int k = 0; k < 8; k++) {
        int j = t + 256 * k;
        float e = s + g_t[tb + j];
        e = e > 0.0f ? e : ALPHA * e;
        e = (arow[j] > 0) ? e : NEG_BIG;
        esh[j] = e;
        mx = fmaxf(mx, e);
    }
    red[t] = mx;
    __syncthreads();
#pragma unroll
    for (int stride = 128; stride; stride >>= 1) {
        if (t < stride) red[t] = fmaxf(red[t], red[t + stride]);
        __syncthreads();
    }
    float m = red[0];
    __syncthreads();

    float sum = 0.0f;
#pragma unroll
    for (int k = 0; k < 8; k++) {
        int j = t + 256 * k;
        sum += __expf(esh[j] - m);           // masked -> exp(~-9e15) == 0
    }
    red[t] = sum;
    __syncthreads();
#pragma unroll
    for (int stride = 128; stride; stride >>= 1) {
        if (t < stride) red[t] += red[t + stride];
        __syncthreads();
    }
    if (t == 0) {
        g_m[row] = m;
        g_linv[row] = 1.0f / red[0];
    }
}

// ---------------------------------------------------------------------------
// Kernel D: out = elu( softmax(P) @ Wh ).
// Block: 256 threads, TILE_I=32 rows of one batch, loop j in tiles of 64.
// Thread owns (irow = t&31, 8 features at fg = t>>5). fp32 accumulators.
// ---------------------------------------------------------------------------
__global__ void __launch_bounds__(256) kD(const int* __restrict__ adj,
                                          float* __restrict__ out) {
    __shared__ float Whsh[64 * 64];          // 16 KB, j-tile of Wh
    __shared__ float psh[32][65];            // padded: conflict-free column read
    __shared__ float tsh[64];
    __shared__ float ssh[32], msh[32];

    int t = threadIdx.x;
    int b = blockIdx.y;
    int i0 = blockIdx.x * 32;

    if (t < 32) {
        int r = b * Nn + i0 + t;
        ssh[t] = g_s[r];
        msh[t] = g_m[r];
    }

    int irow = t & 31;
    int fg = t >> 5;                         // 0..7, 8 features each
    const int* __restrict__ adjb = adj + ((long long)b * Nn + i0) * Nn;
    const float4* __restrict__ Whb =
        (const float4*)(g_Wh + (long long)b * Nn * Ff);

    float acc[8];
#pragma unroll
    for (int q = 0; q < 8; q++) acc[q] = 0.0f;

    __syncthreads();

    for (int j0 = 0; j0 < Nn; j0 += 64) {
        if (t < 64) tsh[t] = g_t[b * Nn + j0 + t];
        // Wh tile rows j0..j0+63 are contiguous: 1024 float4, 4 per thread
        const float4* src = Whb + (size_t)j0 * 16;
#pragma unroll
        for (int k = 0; k < 4; k++)
            ((float4*)Whsh)[t + 256 * k] = src[t + 256 * k];
        __syncthreads();

        // phase 1: p tile (unnormalized softmax numerators)
#pragma unroll
        for (int k = 0; k < 8; k++) {
            int idx = t + 256 * k;           // 0..2047 over 32x64 tile
            int ii = idx >> 6;
            int jj = idx & 63;
            int av = adjb[(size_t)ii * Nn + j0 + jj];
            float e = ssh[ii] + tsh[jj];
            e = e > 0.0f ? e : ALPHA * e;
            float p = (av > 0) ? __expf(e - msh[ii]) : 0.0f;
            psh[ii][jj] = p;
        }
        __syncthreads();

        // phase 2: acc += p * Wh   (Wh reads are warp-broadcast)
#pragma unroll
        for (int jj = 0; jj < 64; jj++) {
            float p = psh[irow][jj];
            float4 w0 = ((float4*)Whsh)[jj * 16 + fg * 2];
            float4 w1 = ((float4*)Whsh)[jj * 16 + fg * 2 + 1];
            acc[0] += p * w0.x; acc[1] += p * w0.y;
            acc[2] += p * w0.z; acc[3] += p * w0.w;
            acc[4] += p * w1.x; acc[5] += p * w1.y;
            acc[6] += p * w1.z; acc[7] += p * w1.w;
        }
        __syncthreads();
    }

    // epilogue: scale by 1/l, ELU
    float linv = g_linv[b * Nn + i0 + irow];
    float* orow = out + ((size_t)b * Nn + i0 + irow) * Ff + fg * 8;
#pragma unroll
    for (int q = 0; q < 8; q++) {
        float x = acc[q] * linv;
        orow[q] = x > 0.0f ? x : (__expf(x) - 1.0f);
    }
}

// ---------------------------------------------------------------------------
extern "C" void kernel_launch(void* const* d_in, const int* in_sizes, int n_in,
                              void* d_out, int out_size) {
    const float* h   = (const float*)d_in[0];   // (8,2048,64) f32
    const int*   adj = (const int*)d_in[1];     // (8,2048,2048) i32
    const float* W   = (const float*)d_in[2];   // (64,64) f32
    const float* a   = (const float*)d_in[3];   // (128,1) f32
    float* out = (float*)d_out;                 // (8,2048,64) f32

    kA<<<(Bb * Nn) / 4, 256>>>(h, W, a);
    kC<<<Bb * Nn, 256>>>(adj);
    kD<<<dim3(Nn / 32, Bb), 256>>>(adj, out);
}

// round 2
// speedup vs baseline: 1.2108x; 1.2108x over previous
#include <cuda_runtime.h>

#define Bb 8
#define Nn 2048
#define Ff 64
#define ALPHA 0.2f

// Scratch (no allocation allowed -> device globals)
__device__ float g_Wh[Bb * Nn * Ff];   // 4 MB
__device__ float g_s[Bb * Nn];
__device__ float g_t[Bb * Nn];
__device__ float g_tmax[Bb];

// packed f32x2 FMA (FFMA2) — not emitted by ptxas from C++
#define FMA2(acc, a, b) \
    asm("fma.rn.f32x2 %0, %1, %2, %0;" : "+l"(acc) : "l"(a), "l"(b))

// ---------------------------------------------------------------------------
// Kernel A: Wh = h @ W ; s = Wh @ a1 ; t = Wh @ a2
// 256 threads, 32 rows per block (W staged once per block).
// ---------------------------------------------------------------------------
__global__ void __launch_bounds__(256) kA(const float* __restrict__ h,
                                          const float* __restrict__ W,
                                          const float* __restrict__ a) {
    __shared__ float Wsh[64 * 64];
    __shared__ float hsh[4][64];
    __shared__ float red[4][2][2];   // [r][s|t][warp-half]

    int t = threadIdx.x;
    int r = t >> 6;
    int o = t & 63;
    int lane = t & 31;
    int half = (t >> 5) & 1;

#pragma unroll
    for (int k = 0; k < 16; k++) Wsh[t + 256 * k] = W[t + 256 * k];
    float a1 = a[o];
    float a2 = a[64 + o];

    for (int iter = 0; iter < 8; iter++) {
        int row = blockIdx.x * 32 + iter * 4 + r;
        __syncthreads();
        hsh[r][o] = h[row * 64 + o];
        __syncthreads();

        float wh = 0.0f;
#pragma unroll
        for (int f = 0; f < 64; f++) wh += hsh[r][f] * Wsh[f * 64 + o];
        g_Wh[row * 64 + o] = wh;

        float sv = wh * a1;
        float tv = wh * a2;
#pragma unroll
        for (int off = 16; off; off >>= 1) {
            sv += __shfl_down_sync(0xffffffffu, sv, off);
            tv += __shfl_down_sync(0xffffffffu, tv, off);
        }
        if (lane == 0) { red[r][0][half] = sv; red[r][1][half] = tv; }
        __syncthreads();
        if (o == 0) {
            g_s[row] = red[r][0][0] + red[r][0][1];
            g_t[row] = red[r][1][0] + red[r][1][1];
        }
    }
}

// ---------------------------------------------------------------------------
// Kernel B: per-batch tmax = max_j t_j   (8 blocks, trivial)
// ---------------------------------------------------------------------------
__global__ void __launch_bounds__(256) kB() {
    __shared__ float red[256];
    int b = blockIdx.x;
    int t = threadIdx.x;
    float m = -1e30f;
#pragma unroll
    for (int k = 0; k < 8; k++) m = fmaxf(m, g_t[b * Nn + t + 256 * k]);
    red[t] = m;
    __syncthreads();
#pragma unroll
    for (int s = 128; s; s >>= 1) {
        if (t < s) red[t] = fmaxf(red[t], red[t + s]);
        __syncthreads();
    }
    if (t == 0) g_tmax[b] = red[0];
}

// ---------------------------------------------------------------------------
// Kernel D: fused masked-softmax + P@Wh + ELU, single pass over adj.
// Uses shift constant m̂_i = lrelu(s_i + tmax_b)  (>= row max; softmax is
// shift-invariant, so result is mathematically identical).
// Block: 256 threads, 32 i-rows, j tiled by 64. f32x2 packed FMA in phase 2.
// ---------------------------------------------------------------------------
__global__ void __launch_bounds__(256) kD(const int* __restrict__ adj,
                                          float* __restrict__ out) {
    __shared__ float Whsh[64 * 64];          // 16 KB j-tile of Wh
    __shared__ float psh[32][65];            // conflict-free column reads
    __shared__ float tsh[64];
    __shared__ float ssh[32], msh[32], linvsh[32];

    int t = threadIdx.x;
    int b = blockIdx.y;
    int i0 = blockIdx.x * 32;

    if (t < 32) {
        float s = g_s[b * Nn + i0 + t];
        ssh[t] = s;
        float e = s + g_tmax[b];
        msh[t] = e > 0.0f ? e : ALPHA * e;   // upper bound of row entries
    }

    int irow = t & 31;                       // phase-2 mapping
    int fg = t >> 5;                         // 0..7, 8 features each
    int p_ii0 = t >> 4;                      // phase-1 mapping: 2 rows/thread
    int p_jj = (t & 15) * 4;                 // 4 consecutive j per thread

    const int* __restrict__ adjb = adj + ((long long)b * Nn + i0) * Nn;
    const float4* __restrict__ Whb =
        (const float4*)(g_Wh + (size_t)b * Nn * Ff);

    unsigned long long acc[4] = {0ull, 0ull, 0ull, 0ull};  // 8 f32 in 4 pairs
    float rsum0 = 0.0f, rsum1 = 0.0f;        // row-sum partials (2 rows)

    __syncthreads();

    for (int j0 = 0; j0 < Nn; j0 += 64) {
        if (t < 64) tsh[t] = g_t[b * Nn + j0 + t];
        const float4* src = Whb + (size_t)j0 * 16;
#pragma unroll
        for (int k = 0; k < 4; k++)
            ((float4*)Whsh)[t + 256 * k] = src[t + 256 * k];
        __syncthreads();

        // phase 1: p tile + row-sum accumulation (int4 adj loads)
#pragma unroll
        for (int k2 = 0; k2 < 2; k2++) {
            int ii = p_ii0 + 16 * k2;
            int4 av = *(const int4*)(adjb + (size_t)ii * Nn + j0 + p_jj);
            float4 tt = *(const float4*)&tsh[p_jj];
            float s = ssh[ii];
            float m = msh[ii];

            float e0 = s + tt.x; e0 = e0 > 0.0f ? e0 : ALPHA * e0;
            float e1 = s + tt.y; e1 = e1 > 0.0f ? e1 : ALPHA * e1;
            float e2 = s + tt.z; e2 = e2 > 0.0f ? e2 : ALPHA * e2;
            float e3 = s + tt.w; e3 = e3 > 0.0f ? e3 : ALPHA * e3;

            float p0 = (av.x > 0) ? __expf(e0 - m) : 0.0f;
            float p1 = (av.y > 0) ? __expf(e1 - m) : 0.0f;
            float p2 = (av.z > 0) ? __expf(e2 - m) : 0.0f;
            float p3 = (av.w > 0) ? __expf(e3 - m) : 0.0f;

            psh[ii][p_jj + 0] = p0;
            psh[ii][p_jj + 1] = p1;
            psh[ii][p_jj + 2] = p2;
            psh[ii][p_jj + 3] = p3;
            float ps = (p0 + p1) + (p2 + p3);
            if (k2 == 0) rsum0 += ps; else rsum1 += ps;
        }
        __syncthreads();

        // phase 2: acc += p * Wh, packed f32x2 FMA
#pragma unroll 16
        for (int jj = 0; jj < 64; jj++) {
            float p = psh[irow][jj];
            unsigned long long pp;
            asm("mov.b64 %0, {%1, %1};" : "=l"(pp) : "f"(p));
            const ulonglong2* w64 =
                (const ulonglong2*)(Whsh + jj * 64 + fg * 8);
            ulonglong2 q0 = w64[0];
            ulonglong2 q1 = w64[1];
            FMA2(acc[0], pp, q0.x);
            FMA2(acc[1], pp, q0.y);
            FMA2(acc[2], pp, q1.x);
            FMA2(acc[3], pp, q1.y);
        }
        __syncthreads();
    }

    // row-sum reduction: partials -> psh[ii][0..15] -> linv
    psh[p_ii0][t & 15] = rsum0;
    psh[p_ii0 + 16][t & 15] = rsum1;
    __syncthreads();
    if (t < 32) {
        float ssum = 0.0f;
#pragma unroll
        for (int j = 0; j < 16; j++) ssum += psh[t][j];
        linvsh[t] = 1.0f / ssum;
    }
    __syncthreads();

    // epilogue: normalize + ELU
    float linv = linvsh[irow];
    float* orow = out + ((size_t)b * Nn + i0 + irow) * Ff + fg * 8;
#pragma unroll
    for (int q = 0; q < 4; q++) {
        float lo, hi;
        asm("mov.b64 {%0, %1}, %2;" : "=f"(lo), "=f"(hi) : "l"(acc[q]));
        float x0 = lo * linv;
        float x1 = hi * linv;
        orow[q * 2 + 0] = x0 > 0.0f ? x0 : (__expf(x0) - 1.0f);
        orow[q * 2 + 1] = x1 > 0.0f ? x1 : (__expf(x1) - 1.0f);
    }
}

// ---------------------------------------------------------------------------
extern "C" void kernel_launch(void* const* d_in, const int* in_sizes, int n_in,
                              void* d_out, int out_size) {
    const float* h   = (const float*)d_in[0];   // (8,2048,64) f32
    const int*   adj = (const int*)d_in[1];     // (8,2048,2048) i32
    const float* W   = (const float*)d_in[2];   // (64,64) f32
    const float* a   = (const float*)d_in[3];   // (128,1) f32
    float* out = (float*)d_out;                 // (8,2048,64) f32

    kA<<<(Bb * Nn) / 32, 256>>>(h, W, a);
    kB<<<Bb, 256>>>();
    kD<<<dim3(Nn / 32, Bb), 256>>>(adj, out);
}

// round 5
// speedup vs baseline: 2.7088x; 2.2371x over previous
#include <cuda_runtime.h>
#include <cuda_fp16.h>
#include <cstdint>

#define Bb 8
#define Nn 2048
#define ALPHA 0.2f

// ---------------- device globals (no allocation allowed) -------------------
__device__ float  g_s[Bb * Nn];
__device__ float  g_t[Bb * Nn];
__device__ float  g_tmax[Bb];
__device__ __half g_WhT[Bb * 64 * Nn];   // [b][f][j], fp16, 2MB

// ---------------- PTX helpers ----------------------------------------------
__device__ __forceinline__ uint32_t su32(const void* p) {
    uint32_t a;
    asm("{ .reg .u64 t; cvta.to.shared.u64 t, %1; cvt.u32.u64 %0, t; }"
        : "=r"(a) : "l"(p));
    return a;
}
// pack two f32 -> f16x2 (lo, hi)
#define CVTH2(r, lo, hi) \
    asm("cvt.rn.f16x2.f32 %0, %2, %1;" : "=r"(r) : "f"(lo), "f"(hi))

#define LDSM4(r0, r1, r2, r3, addr) \
    asm volatile("ldmatrix.sync.aligned.m8n8.x4.shared.b16 {%0,%1,%2,%3}, [%4];" \
                 : "=r"(r0), "=r"(r1), "=r"(r2), "=r"(r3) : "r"(addr))

#define MMA16816(dd, a0, a1, a2, a3, b0, b1) \
    asm volatile("mma.sync.aligned.m16n8k16.row.col.f32.f16.f16.f32 " \
                 "{%0,%1,%2,%3}, {%4,%5,%6,%7}, {%8,%9}, {%0,%1,%2,%3};" \
                 : "+f"((dd)[0]), "+f"((dd)[1]), "+f"((dd)[2]), "+f"((dd)[3]) \
                 : "r"(a0), "r"(a1), "r"(a2), "r"(a3), "r"(b0), "r"(b1))

// ---------------------------------------------------------------------------
// Kernel A: Wh = h @ W (f32 regs); emits s, t (f32) and WhT (fp16, [b][f][j]).
// 256 thr, 32 rows/block, 4 rows per thread (register blocked).
// ---------------------------------------------------------------------------
__global__ void __launch_bounds__(256) kA(const float* __restrict__ h,
                                          const float* __restrict__ W,
                                          const float* __restrict__ a) {
    __shared__ float  Wsh[64 * 64];
    __shared__ float  hsh[16][64];
    __shared__ float  red[16][2][2];
    __shared__ __half Tsh[64][40];          // padded rows: 80B (16B aligned)

    int t = threadIdx.x;
    int o = t & 63, rg = t >> 6;
    int lane = t & 31, hw = (t >> 5) & 1;
    int blk = blockIdx.x;

#pragma unroll
    for (int k = 0; k < 16; k++) Wsh[t + 256 * k] = W[t + 256 * k];
    float a1 = a[o], a2 = a[64 + o];

#pragma unroll
    for (int iter = 0; iter < 2; iter++) {
        __syncthreads();
        {
            int rr = t >> 4, f4 = t & 15;
            *(float4*)&hsh[rr][f4 * 4] =
                *(const float4*)(h + (size_t)(blk * 32 + iter * 16 + rr) * 64 + f4 * 4);
        }
        __syncthreads();

        float acc[4] = {0.f, 0.f, 0.f, 0.f};
#pragma unroll
        for (int f4 = 0; f4 < 16; f4++) {
            float w0 = Wsh[(f4 * 4 + 0) * 64 + o];
            float w1 = Wsh[(f4 * 4 + 1) * 64 + o];
            float w2 = Wsh[(f4 * 4 + 2) * 64 + o];
            float w3 = Wsh[(f4 * 4 + 3) * 64 + o];
#pragma unroll
            for (int r = 0; r < 4; r++) {
                float4 hv = *(const float4*)&hsh[rg * 4 + r][f4 * 4];
                acc[r] += hv.x * w0 + hv.y * w1 + hv.z * w2 + hv.w * w3;
            }
        }
        int jloc = iter * 16 + rg * 4;
        *(half2*)&Tsh[o][jloc]     = __floats2half2_rn(acc[0], acc[1]);
        *(half2*)&Tsh[o][jloc + 2] = __floats2half2_rn(acc[2], acc[3]);

#pragma unroll
        for (int r = 0; r < 4; r++) {
            float sv = acc[r] * a1;
            float tv = acc[r] * a2;
#pragma unroll
            for (int off = 16; off; off >>= 1) {
                sv += __shfl_down_sync(0xffffffffu, sv, off);
                tv += __shfl_down_sync(0xffffffffu, tv, off);
            }
            if (lane == 0) { red[rg * 4 + r][hw][0] = sv; red[rg * 4 + r][hw][1] = tv; }
        }
        __syncthreads();
        if (t < 16) {
            int row = blk * 32 + iter * 16 + t;
            g_s[row] = red[t][0][0] + red[t][1][0];
            g_t[row] = red[t][0][1] + red[t][1][1];
        }
    }
    __syncthreads();
    {   // write WhT tile: 64 f-rows x 32 j (64B per row)
        int f = t >> 2, c = t & 3;
        uint4 v = *(const uint4*)&Tsh[f][c * 8];
        int b  = (blk * 32) >> 11;
        int j0 = (blk * 32) & 2047;
        *(uint4*)(g_WhT + (size_t)(b * 64 + f) * Nn + j0 + c * 8) = v;
    }
}

// ---------------------------------------------------------------------------
// Kernel B: per-batch tmax
// ---------------------------------------------------------------------------
__global__ void __launch_bounds__(256) kB() {
    __shared__ float red[256];
    int b = blockIdx.x, t = threadIdx.x;
    float m = -1e30f;
#pragma unroll
    for (int k = 0; k < 8; k++) m = fmaxf(m, g_t[b * Nn + t + 256 * k]);
    red[t] = m;
    __syncthreads();
#pragma unroll
    for (int s = 128; s; s >>= 1) {
        if (t < s) red[t] = fmaxf(red[t], red[t + s]);
        __syncthreads();
    }
    if (t == 0) g_tmax[b] = red[0];
}

// ---------------------------------------------------------------------------
// Kernel D: fused masked softmax + HMMA P@Wh + ELU, single adj pass.
// Block: 256 thr (8 warps), i-tile = 128 rows, j-tiles of 64 (K-dim).
// p = adj ? max(A_i*B_j, A'_i*B'_j) : 0  (exact: exp(lrelu(x)-m) with exp
// monotone; m_i = lrelu(s_i + tmax) >= row max; softmax shift-invariant).
// Warp w computes rows [w*16, w*16+16) x all 64 features via mma.m16n8k16.
// ---------------------------------------------------------------------------
#define PSTR 72                         // psh row stride in halves (144B)
#define OFF_PSH  0                      // 128 x 144B = 18432
#define OFF_WSH  18432                  // 64 x 144B  = 9216
#define OFF_TB   27648                  // 2048 f32
#define OFF_TBP  35840                  // 2048 f32
#define OFF_SA   44032                  // 128 f32
#define OFF_SAP  44544                  // 128 f32
#define OFF_RS   45056                  // 256 f32
#define OFF_LINV 46080                  // 128 f32
#define SMEM_TOT 46592                  // < 48KB default limit

__global__ void __launch_bounds__(256) kD(const int* __restrict__ adj,
                                          float* __restrict__ out) {
    extern __shared__ char sm[];
    __half* psh = (__half*)(sm + OFF_PSH);
    __half* wsh = (__half*)(sm + OFF_WSH);
    float*  tB  = (float*)(sm + OFF_TB);
    float*  tBp = (float*)(sm + OFF_TBP);
    float*  sA  = (float*)(sm + OFF_SA);
    float*  sAp = (float*)(sm + OFF_SAP);
    float*  rs  = (float*)(sm + OFF_RS);
    float*  lin = (float*)(sm + OFF_LINV);

    int t = threadIdx.x, w = t >> 5, lane = t & 31;
    int b = blockIdx.y, i0 = blockIdx.x * 128;
    float tmax = g_tmax[b];

    // prologue: exp tables for all 2048 j and 128 i
#pragma unroll
    for (int q = 0; q < 8; q++) {
        int j = t + 256 * q;
        float dd = g_t[b * Nn + j] - tmax;
        tB[j]  = __expf(dd);
        tBp[j] = __expf(ALPHA * dd);
    }
    if (t < 128) {
        float x = g_s[b * Nn + i0 + t] + tmax;
        float m = fmaxf(x, ALPHA * x);
        sA[t]  = __expf(x - m);
        sAp[t] = __expf(ALPHA * x - m);
    }

    int i = t >> 1, jb = (t & 1) * 32;   // phase-1 mapping: row i, 32 j's
    const int* ap = adj + (size_t)(b * Nn + i0 + i) * Nn + jb;
    const __half* whb = g_WhT + (size_t)b * 64 * Nn;

    int4 areg[8];
#pragma unroll
    for (int q = 0; q < 8; q++) areg[q] = *(const int4*)(ap + q * 4);
    __syncthreads();
    float Ai = sA[i], Api = sAp[i];
    float rsum = 0.f;
    float d[8][4];
#pragma unroll
    for (int nb = 0; nb < 8; nb++)
#pragma unroll
        for (int q = 0; q < 4; q++) d[nb][q] = 0.f;

    uint32_t psh_u = su32(psh), wsh_u = su32(wsh);
    // ldmatrix address components (constant across tiles)
    uint32_t a_addr = psh_u + (w * 16 + (lane & 15)) * (PSTR * 2) + (lane >> 4) * 16;
    int mi = lane >> 3, r8 = lane & 7;
    uint32_t b_row_off = ((mi >> 1) * 8 + r8) * (PSTR * 2) + (mi & 1) * 16;

    for (int k = 0; k < 32; k++) {
        int j0 = k * 64;
        // Wh tile: 64 f-rows x 64 j halves (128B rows, stride 144B)
        {
            int f = t >> 3, cc = t & 7;
            uint4 v0 = *(const uint4*)(whb + (size_t)f * Nn + j0 + cc * 8);
            uint4 v1 = *(const uint4*)(whb + (size_t)(f + 32) * Nn + j0 + cc * 8);
            *(uint4*)(wsh + f * PSTR + cc * 8) = v0;
            *(uint4*)(wsh + (f + 32) * PSTR + cc * 8) = v1;
        }
        // P tile from prefetched adj regs
        {
            const float4* B4  = (const float4*)(tB + j0 + jb);
            const float4* Bp4 = (const float4*)(tBp + j0 + jb);
            __half* prow = psh + i * PSTR + jb;
#pragma unroll
            for (int g = 0; g < 4; g++) {
                int4 a0 = areg[g * 2], a1 = areg[g * 2 + 1];
                float4 b0 = B4[g * 2],  b1 = B4[g * 2 + 1];
                float4 c0 = Bp4[g * 2], c1 = Bp4[g * 2 + 1];
                float p0 = (a0.x > 0) ? fmaxf(Ai * b0.x, Api * c0.x) : 0.f;
                float p1 = (a0.y > 0) ? fmaxf(Ai * b0.y, Api * c0.y) : 0.f;
                float p2 = (a0.z > 0) ? fmaxf(Ai * b0.z, Api * c0.z) : 0.f;
                float p3 = (a0.w > 0) ? fmaxf(Ai * b0.w, Api * c0.w) : 0.f;
                float p4 = (a1.x > 0) ? fmaxf(Ai * b1.x, Api * c1.x) : 0.f;
                float p5 = (a1.y > 0) ? fmaxf(Ai * b1.y, Api * c1.y) : 0.f;
                float p6 = (a1.z > 0) ? fmaxf(Ai * b1.z, Api * c1.z) : 0.f;
                float p7 = (a1.w > 0) ? fmaxf(Ai * b1.w, Api * c1.w) : 0.f;
                uint4 pk;
                CVTH2(pk.x, p0, p1); CVTH2(pk.y, p2, p3);
                CVTH2(pk.z, p4, p5); CVTH2(pk.w, p6, p7);
                *(uint4*)(prow + g * 8) = pk;
                rsum += ((p0 + p1) + (p2 + p3)) + ((p4 + p5) + (p6 + p7));
            }
        }
        // prefetch next tile's adj (overlaps with mma below)
        if (k < 31) {
            const int* apn = ap + j0 + 64;
#pragma unroll
            for (int q = 0; q < 8; q++) areg[q] = *(const int4*)(apn + q * 4);
        }
        __syncthreads();

        // mma: warp w does rows w*16..+15, all 64 features, K=64 in 4 steps
#pragma unroll
        for (int kc = 0; kc < 4; kc++) {
            uint32_t a0, a1, a2, a3;
            LDSM4(a0, a1, a2, a3, a_addr + kc * 32);
#pragma unroll
            for (int nbp = 0; nbp < 4; nbp++) {
                uint32_t q0, q1, q2, q3;
                uint32_t baddr = wsh_u + nbp * 16 * (PSTR * 2) + b_row_off + kc * 32;
                LDSM4(q0, q1, q2, q3, baddr);
                MMA16816(d[nbp * 2],     a0, a1, a2, a3, q0, q1);
                MMA16816(d[nbp * 2 + 1], a0, a1, a2, a3, q2, q3);
            }
        }
        __syncthreads();
    }

    // row sums -> linv
    rs[i * 2 + (t & 1)] = rsum;
    __syncthreads();
    if (t < 128) lin[t] = 1.0f / (rs[t * 2] + rs[t * 2 + 1]);
    __syncthreads();

    // epilogue: d-frag rows r0 = w*16 + lane/4, r1 = r0+8; cols nb*8+2*(lane%4)
    int r0 = w * 16 + (lane >> 2);
    int r1 = r0 + 8;
    float l0 = lin[r0], l1 = lin[r1];
    float* o0 = out + (size_t)(b * Nn + i0 + r0) * 64 + (lane & 3) * 2;
    float* o1 = out + (size_t)(b * Nn + i0 + r1) * 64 + (lane & 3) * 2;
#pragma unroll
    for (int nb = 0; nb < 8; nb++) {
        float x0 = d[nb][0] * l0, x1 = d[nb][1] * l0;
        float y0 = d[nb][2] * l1, y1 = d[nb][3] * l1;
        float2 v0, v1;
        v0.x = x0 > 0.f ? x0 : expm1f(x0);
        v0.y = x1 > 0.f ? x1 : expm1f(x1);
        v1.x = y0 > 0.f ? y0 : expm1f(y0);
        v1.y = y1 > 0.f ? y1 : expm1f(y1);
        *(float2*)(o0 + nb * 8) = v0;
        *(float2*)(o1 + nb * 8) = v1;
    }
}

// ---------------------------------------------------------------------------
extern "C" void kernel_launch(void* const* d_in, const int* in_sizes, int n_in,
                              void* d_out, int out_size) {
    const float* h   = (const float*)d_in[0];   // (8,2048,64) f32
    const int*   adj = (const int*)d_in[1];     // (8,2048,2048) i32
    const float* W   = (const float*)d_in[2];   // (64,64) f32
    const float* a   = (const float*)d_in[3];   // (128,1) f32
    float* out = (float*)d_out;                 // (8,2048,64) f32

    kA<<<(Bb * Nn) / 32, 256>>>(h, W, a);
    kB<<<Bb, 256>>>();
    kD<<<dim3(Nn / 128, Bb), 256, SMEM_TOT>>>(adj, out);
}